// round 1
// baseline (speedup 1.0000x reference)
#include <cuda_runtime.h>

// ---------------- problem constants ----------------
#define BW     1024          // windows * batch
#define NTOK   49            // tokens per window
#define CDIM   384           // channels
#define NHEAD  12
#define HD     32
#define MROWS  (BW * NTOK)   // 50176
#define OS     19267584      // 50176*384, one output-stream stride
#define ATTN_SCALE 0.17677669529663687f   // 32^-0.5

// ---------------- scratch (device globals; no allocation allowed) ----------
__device__ float g_qkv[57802752];   // [50176, 1152]  (3,H,HD) column layout
__device__ float g_vs [19267584];   // [50176, 384]
__device__ float g_vsh[19267584];   // [50176, 384]
__device__ float g_o  [57802752];   // 3 x [50176, 384] (o_x, o_scale, o_shift)

// =====================================================================
// SGEMM: C[M,N] = A[M,K] @ W[K,N] + bias[N]
// Tile 128x128x8, 256 threads, 8x8 register tile per thread.
// Requires: M % 128 == 0, N % 128 == 0, K % 8 == 0 (all true here).
// =====================================================================
__global__ __launch_bounds__(256) void sgemm_bias_kernel(
    const float* __restrict__ A, const float* __restrict__ W,
    const float* __restrict__ bias, float* __restrict__ C,
    int N, int K)
{
    __shared__ float As[8][128];
    __shared__ float Bs[8][128];

    const int tid = threadIdx.x;
    const int tx  = tid & 15;        // 0..15 -> 8-col group
    const int ty  = tid >> 4;        // 0..15 -> 8-row group
    const int bm  = blockIdx.y << 7;
    const int bn  = blockIdx.x << 7;

    const int arow = tid >> 1;            // 0..127
    const int ak   = (tid & 1) << 2;      // 0 or 4
    const int brow = tid >> 5;            // 0..7
    const int bcol = (tid & 31) << 2;     // 0..124

    const float* Aptr = A + (size_t)(bm + arow) * K + ak;
    const float* Wptr = W + (size_t)brow * N + bn + bcol;

    float acc[8][8];
#pragma unroll
    for (int i = 0; i < 8; i++)
#pragma unroll
        for (int j = 0; j < 8; j++) acc[i][j] = 0.f;

    for (int kb = 0; kb < K; kb += 8) {
        float4 a4 = *(const float4*)(Aptr + kb);
        float4 b4 = *(const float4*)(Wptr + (size_t)kb * N);
        As[ak + 0][arow] = a4.x;
        As[ak + 1][arow] = a4.y;
        As[ak + 2][arow] = a4.z;
        As[ak + 3][arow] = a4.w;
        *(float4*)&Bs[brow][bcol] = b4;
        __syncthreads();

#pragma unroll
        for (int kk = 0; kk < 8; kk++) {
            float ar[8], br[8];
            *(float4*)(ar)     = *(const float4*)&As[kk][ty * 8];
            *(float4*)(ar + 4) = *(const float4*)&As[kk][ty * 8 + 4];
            *(float4*)(br)     = *(const float4*)&Bs[kk][tx * 8];
            *(float4*)(br + 4) = *(const float4*)&Bs[kk][tx * 8 + 4];
#pragma unroll
            for (int i = 0; i < 8; i++)
#pragma unroll
                for (int j = 0; j < 8; j++)
                    acc[i][j] += ar[i] * br[j];
        }
        __syncthreads();
    }

    float bv[8];
    *(float4*)(bv)     = *(const float4*)(bias + bn + tx * 8);
    *(float4*)(bv + 4) = *(const float4*)(bias + bn + tx * 8 + 4);

#pragma unroll
    for (int i = 0; i < 8; i++) {
        size_t row = (size_t)(bm + ty * 8 + i);
        float4 o0 = make_float4(acc[i][0] + bv[0], acc[i][1] + bv[1],
                                acc[i][2] + bv[2], acc[i][3] + bv[3]);
        float4 o1 = make_float4(acc[i][4] + bv[4], acc[i][5] + bv[5],
                                acc[i][6] + bv[6], acc[i][7] + bv[7]);
        *(float4*)(C + row * N + bn + tx * 8)     = o0;
        *(float4*)(C + row * N + bn + tx * 8 + 4) = o1;
    }
}

// =====================================================================
// Attention: one block per (window, head). 256 threads.
//  - loads q,k (padded rows of 36 floats), v / v_scale / v_shift (rows of 32)
//  - QK^T with K-row cached in registers (conflict-free q reads)
//  - +rpb (recomputed index) + mask, softmax (thread per row)
//  - AV for all three streams simultaneously, float4 output
// =====================================================================
__global__ __launch_bounds__(256) void attn_kernel(
    const float* __restrict__ mask, const float* __restrict__ rpb)
{
    const int w = blockIdx.x;     // 0..1023
    const int h = blockIdx.y;     // 0..11

    __shared__ float sq  [49 * 36];
    __shared__ float sk  [49 * 36];
    __shared__ float sv  [49 * 32];
    __shared__ float svs [49 * 32];
    __shared__ float svsh[49 * 32];
    __shared__ float sattn[49 * 49];
    __shared__ float srpb[169];

    const int tid = threadIdx.x;

    const float* qbase = g_qkv + (size_t)w * 49 * 1152 + h * 32;
    const float* vsb   = g_vs  + (size_t)w * 49 * 384 + h * 32;
    const float* vshb  = g_vsh + (size_t)w * 49 * 384 + h * 32;

    // stage rpb column for this head
    for (int idx = tid; idx < 169; idx += 256)
        srpb[idx] = rpb[idx * 12 + h];

    // stage q,k,v,vs,vsh
    for (int idx = tid; idx < 49 * 8; idx += 256) {
        int n = idx >> 3;
        int c = (idx & 7) << 2;
        float4 q4 = *(const float4*)(qbase + (size_t)n * 1152 + c);
        float4 k4 = *(const float4*)(qbase + (size_t)n * 1152 + 384 + c);
        float4 v4 = *(const float4*)(qbase + (size_t)n * 1152 + 768 + c);
        float4 s4 = *(const float4*)(vsb  + (size_t)n * 384 + c);
        float4 t4 = *(const float4*)(vshb + (size_t)n * 384 + c);
        *(float4*)&sq  [n * 36 + c] = q4;
        *(float4*)&sk  [n * 36 + c] = k4;
        *(float4*)&sv  [n * 32 + c] = v4;
        *(float4*)&svs [n * 32 + c] = s4;
        *(float4*)&svsh[n * 32 + c] = t4;
    }
    __syncthreads();

    // ---- QK^T + rpb + mask ----
    const float* mrow = mask + (size_t)(w & 15) * 2401;
    if (tid < 245) {
        const int j    = tid / 5;
        const int isub = tid - j * 5;
        const int yj = j / 7, xj = j - yj * 7;

        float kr[32];
#pragma unroll
        for (int c = 0; c < 8; c++) {
            float4 k4 = *(const float4*)&sk[j * 36 + c * 4];
            kr[c * 4 + 0] = k4.x; kr[c * 4 + 1] = k4.y;
            kr[c * 4 + 2] = k4.z; kr[c * 4 + 3] = k4.w;
        }

#pragma unroll
        for (int t = 0; t < 10; t++) {
            int i = isub + t * 5;
            if (i < 49) {
                float acc = 0.f;
#pragma unroll
                for (int c = 0; c < 8; c++) {
                    float4 q4 = *(const float4*)&sq[i * 36 + c * 4];
                    acc += q4.x * kr[c * 4 + 0] + q4.y * kr[c * 4 + 1]
                         + q4.z * kr[c * 4 + 2] + q4.w * kr[c * 4 + 3];
                }
                int yi = i / 7, xi = i - yi * 7;
                int ridx = (yi - yj + 6) * 13 + (xi - xj + 6);
                sattn[i * 49 + j] = acc * ATTN_SCALE + srpb[ridx] + mrow[i * 49 + j];
            }
        }
    }
    __syncthreads();

    // ---- softmax per row ----
    if (tid < 49) {
        float m = -1e30f;
#pragma unroll
        for (int jj = 0; jj < 49; jj++) m = fmaxf(m, sattn[tid * 49 + jj]);
        float s = 0.f;
#pragma unroll
        for (int jj = 0; jj < 49; jj++) {
            float e = __expf(sattn[tid * 49 + jj] - m);
            sattn[tid * 49 + jj] = e;
            s += e;
        }
        float inv = 1.f / s;
#pragma unroll
        for (int jj = 0; jj < 49; jj++) sattn[tid * 49 + jj] *= inv;
    }
    __syncthreads();

    // ---- AV for 3 streams ----
    const size_t obase = (size_t)w * 49 * 384 + h * 32;
    for (int idx = tid; idx < 392; idx += 256) {
        int i  = idx >> 3;
        int d4 = (idx & 7) << 2;
        float4 a0 = make_float4(0.f, 0.f, 0.f, 0.f);
        float4 a1 = a0, a2 = a0;
#pragma unroll
        for (int j = 0; j < 49; j++) {
            float a = sattn[i * 49 + j];
            float4 v4 = *(const float4*)&sv  [j * 32 + d4];
            float4 s4 = *(const float4*)&svs [j * 32 + d4];
            float4 t4 = *(const float4*)&svsh[j * 32 + d4];
            a0.x += a * v4.x; a0.y += a * v4.y; a0.z += a * v4.z; a0.w += a * v4.w;
            a1.x += a * s4.x; a1.y += a * s4.y; a1.z += a * s4.z; a1.w += a * s4.w;
            a2.x += a * t4.x; a2.y += a * t4.y; a2.z += a * t4.z; a2.w += a * t4.w;
        }
        size_t off = obase + (size_t)i * 384 + d4;
        *(float4*)&g_o[off]          = a0;
        *(float4*)&g_o[OS + off]     = a1;
        *(float4*)&g_o[2 * OS + off] = a2;
    }
}

// =====================================================================
// launch
// =====================================================================
extern "C" void kernel_launch(void* const* d_in, const int* in_sizes, int n_in,
                              void* d_out, int out_size)
{
    (void)in_sizes; (void)n_in; (void)out_size;

    const float* x            = (const float*)d_in[0];
    const float* scale        = (const float*)d_in[1];
    const float* shift        = (const float*)d_in[2];
    const float* mask         = (const float*)d_in[3];
    const float* qkv_w        = (const float*)d_in[4];
    const float* qkv_b        = (const float*)d_in[5];
    const float* vscale_w     = (const float*)d_in[6];
    const float* vscale_b     = (const float*)d_in[7];
    const float* vshift_w     = (const float*)d_in[8];
    const float* vshift_b     = (const float*)d_in[9];
    const float* rpb_table    = (const float*)d_in[10];
    const float* proj_x_w     = (const float*)d_in[11];
    const float* proj_x_b     = (const float*)d_in[12];
    const float* proj_scale_w = (const float*)d_in[13];
    const float* proj_scale_b = (const float*)d_in[14];
    const float* proj_shift_w = (const float*)d_in[15];
    const float* proj_shift_b = (const float*)d_in[16];
    float* out = (float*)d_out;

    float *p_qkv, *p_vs, *p_vsh, *p_o;
    cudaGetSymbolAddress((void**)&p_qkv, g_qkv);
    cudaGetSymbolAddress((void**)&p_vs,  g_vs);
    cudaGetSymbolAddress((void**)&p_vsh, g_vsh);
    cudaGetSymbolAddress((void**)&p_o,   g_o);

    dim3 blk(256);
    dim3 g_qkvgrid(1152 / 128, MROWS / 128);   // 9 x 392
    dim3 g_384grid(384 / 128, MROWS / 128);    // 3 x 392

    // input projections
    sgemm_bias_kernel<<<g_qkvgrid, blk>>>(x,     qkv_w,    qkv_b,    p_qkv, 1152, CDIM);
    sgemm_bias_kernel<<<g_384grid, blk>>>(scale, vscale_w, vscale_b, p_vs,  384,  CDIM);
    sgemm_bias_kernel<<<g_384grid, blk>>>(shift, vshift_w, vshift_b, p_vsh, 384,  CDIM);

    // attention (all heads/windows, 3 value streams)
    dim3 agrid(BW, NHEAD);
    attn_kernel<<<agrid, blk>>>(mask, rpb_table);

    // output projections straight into d_out (x, scale, shift contiguous)
    sgemm_bias_kernel<<<g_384grid, blk>>>(p_o,          proj_x_w,     proj_x_b,     out,          384, CDIM);
    sgemm_bias_kernel<<<g_384grid, blk>>>(p_o + OS,     proj_scale_w, proj_scale_b, out + OS,     384, CDIM);
    sgemm_bias_kernel<<<g_384grid, blk>>>(p_o + 2 * OS, proj_shift_w, proj_shift_b, out + 2 * OS, 384, CDIM);
}

// round 3
// speedup vs baseline: 1.3039x; 1.3039x over previous
#include <cuda_runtime.h>
#include <cuda_bf16.h>
#include <cstdint>

// ---------------- problem constants ----------------
#define BW     1024          // windows * batch
#define NTOK   49            // tokens per window
#define CDIM   384           // channels (K of every GEMM)
#define NHEAD  12
#define HD     32
#define MROWS  (BW * NTOK)   // 50176
#define OS     19267584      // 50176*384, one output-stream stride
#define ATTN_SCALE 0.17677669529663687f   // 32^-0.5

// ---------------- scratch (device globals; no allocation allowed) ----------
__device__ float g_qkv[57802752];   // [50176, 1152]
__device__ float g_vs [19267584];   // [50176, 384]
__device__ float g_vsh[19267584];   // [50176, 384]
__device__ float g_o  [57802752];   // 3 x [50176, 384]

// =====================================================================
// mma.sync helpers (sm_80+ => valid on sm_103 base target)
// =====================================================================
__device__ __forceinline__ uint32_t smem_u32(const void* p) {
    uint32_t a;
    asm("{ .reg .u64 t; cvta.to.shared.u64 t, %1; cvt.u32.u64 %0, t; }" : "=r"(a) : "l"(p));
    return a;
}
__device__ __forceinline__ void ldsm_x4(uint32_t* r, uint32_t addr) {
    asm volatile("ldmatrix.sync.aligned.m8n8.x4.shared.b16 {%0,%1,%2,%3}, [%4];"
        : "=r"(r[0]), "=r"(r[1]), "=r"(r[2]), "=r"(r[3]) : "r"(addr));
}
__device__ __forceinline__ void ldsm_x2t(uint32_t* r, uint32_t addr) {
    asm volatile("ldmatrix.sync.aligned.m8n8.x2.trans.shared.b16 {%0,%1}, [%2];"
        : "=r"(r[0]), "=r"(r[1]) : "r"(addr));
}
__device__ __forceinline__ void mma16816(float* d, const uint32_t* a, const uint32_t* b) {
    asm volatile("mma.sync.aligned.m16n8k16.row.col.f32.bf16.bf16.f32 "
        "{%0,%1,%2,%3}, {%4,%5,%6,%7}, {%8,%9}, {%0,%1,%2,%3};"
        : "+f"(d[0]), "+f"(d[1]), "+f"(d[2]), "+f"(d[3])
        : "r"(a[0]), "r"(a[1]), "r"(a[2]), "r"(a[3]), "r"(b[0]), "r"(b[1]));
}

// pack 2 floats into bf16x2 hi parts and lo residual parts
__device__ __forceinline__ void split2(float x, float y, uint32_t& hi, uint32_t& lo) {
    __nv_bfloat16 hx = __float2bfloat16(x);
    __nv_bfloat16 hy = __float2bfloat16(y);
    __nv_bfloat162 hp = __halves2bfloat162(hx, hy);
    __nv_bfloat162 lp = __halves2bfloat162(__float2bfloat16(x - __bfloat162float(hx)),
                                           __float2bfloat16(y - __bfloat162float(hy)));
    hi = *(uint32_t*)&hp;
    lo = *(uint32_t*)&lp;
}

// ---------------- smem layout (bytes, per stage) ----------------
// AsHi [128][40] bf16 = 10240 B ; AsLo same ; BsHi [32][136] bf16 = 8704 B ; BsLo same
#define AS_HI   0
#define AS_LO   10240
#define BS_HI   20480
#define BS_LO   29184
#define STAGE_B 37888
#define GEMM_SMEM_BYTES (2 * STAGE_B)

// =====================================================================
// split-bf16 tensor-core GEMM: C[M,N] = A[M,384] @ W[384,N] + bias
// grid = (N/128, M/128), 256 threads. 3-term hi/lo MMA, K-chunk 32,
// double-buffered smem with register prefetch.
// =====================================================================
__global__ void __launch_bounds__(256, 1) gemm_mma_kernel(
    const float* __restrict__ A, const float* __restrict__ W,
    const float* __restrict__ bias, float* __restrict__ C, int N)
{
    extern __shared__ char sm[];
    const uint32_t sb = smem_u32(sm);

    const int tid  = threadIdx.x;
    const int lane = tid & 31;
    const int wid  = tid >> 5;
    const int wm   = wid >> 1;       // 0..3  (M warp)
    const int wn   = wid & 1;        // 0..1  (N warp)
    const int bm   = blockIdx.y << 7;
    const int bn   = blockIdx.x << 7;

    // ---- staging addresses (per-thread) ----
    const int arow = tid >> 1;               // 0..127
    const int acol = (tid & 1) << 4;         // 0 or 16 (floats)
    const int brow = tid >> 3;               // 0..31   (k)
    const int bcol = (tid & 7) << 4;         // 0..112  (n, 16 floats)

    const float* Ag = A + (size_t)(bm + arow) * CDIM + acol;
    const float* Wg = W + (size_t)brow * N + bn + bcol;

    float4 apf[4], bpf[4];
#pragma unroll
    for (int i = 0; i < 4; i++) {
        apf[i] = *(const float4*)(Ag + i * 4);
        bpf[i] = *(const float4*)(Wg + i * 4);
    }

    float acc[2][8][4];
#pragma unroll
    for (int mi = 0; mi < 2; mi++)
#pragma unroll
        for (int ni = 0; ni < 8; ni++)
#pragma unroll
            for (int r = 0; r < 4; r++) acc[mi][ni][r] = 0.f;

    // fragment base addresses (byte offsets within a stage)
    const uint32_t aoff = (uint32_t)(((wm * 32 + (lane & 15)) * 40 + ((lane >> 4) << 3)) << 1);
    const uint32_t boff = (uint32_t)(((lane & 15) * 136 + wn * 64) << 1);

    const int NCHUNK = CDIM / 32;   // 12

    for (int kc = 0; kc < NCHUNK; kc++) {
        const uint32_t st = sb + (uint32_t)(kc & 1) * STAGE_B;

        // ---- store prefetched chunk kc into stage ----
        {
            uint32_t* ah = (uint32_t*)(sm + (kc & 1) * STAGE_B + AS_HI) + arow * 20 + (acol >> 1);
            uint32_t* al = (uint32_t*)(sm + (kc & 1) * STAGE_B + AS_LO) + arow * 20 + (acol >> 1);
            uint32_t* bh = (uint32_t*)(sm + (kc & 1) * STAGE_B + BS_HI) + brow * 68 + (bcol >> 1);
            uint32_t* bl = (uint32_t*)(sm + (kc & 1) * STAGE_B + BS_LO) + brow * 68 + (bcol >> 1);
#pragma unroll
            for (int i = 0; i < 4; i++) {
                uint32_t h0, l0, h1, l1;
                split2(apf[i].x, apf[i].y, h0, l0);
                split2(apf[i].z, apf[i].w, h1, l1);
                ah[i * 2] = h0; ah[i * 2 + 1] = h1;
                al[i * 2] = l0; al[i * 2 + 1] = l1;
                split2(bpf[i].x, bpf[i].y, h0, l0);
                split2(bpf[i].z, bpf[i].w, h1, l1);
                bh[i * 2] = h0; bh[i * 2 + 1] = h1;
                bl[i * 2] = l0; bl[i * 2 + 1] = l1;
            }
        }
        __syncthreads();

        // ---- prefetch next chunk ----
        if (kc + 1 < NCHUNK) {
#pragma unroll
            for (int i = 0; i < 4; i++) {
                apf[i] = *(const float4*)(Ag + (kc + 1) * 32 + i * 4);
                bpf[i] = *(const float4*)(Wg + (size_t)(kc + 1) * 32 * N + i * 4);
            }
        }

        // ---- compute 2 x k16 steps ----
#pragma unroll
        for (int ks = 0; ks < 2; ks++) {
            uint32_t ah[2][4], al[2][4];
            ldsm_x4(ah[0], st + AS_HI + aoff + ks * 32);
            ldsm_x4(ah[1], st + AS_HI + aoff + ks * 32 + 16 * 80);
            ldsm_x4(al[0], st + AS_LO + aoff + ks * 32);
            ldsm_x4(al[1], st + AS_LO + aoff + ks * 32 + 16 * 80);
            const uint32_t bks = st + boff + (uint32_t)(ks * 16 * 272);
#pragma unroll
            for (int ni = 0; ni < 8; ni++) {
                uint32_t bh[2], bl[2];
                ldsm_x2t(bh, bks + BS_HI + ni * 16);
                ldsm_x2t(bl, bks + BS_LO + ni * 16);
                mma16816(acc[0][ni], ah[0], bh);
                mma16816(acc[1][ni], ah[1], bh);
                mma16816(acc[0][ni], al[0], bh);
                mma16816(acc[1][ni], al[1], bh);
                mma16816(acc[0][ni], ah[0], bl);
                mma16816(acc[1][ni], ah[1], bl);
            }
        }
        __syncthreads();
    }

    // ---- epilogue: bias add + store ----
    const int mrow0 = bm + wm * 32 + (lane >> 2);
    const int ncol0 = bn + wn * 64 + ((lane & 3) << 1);
#pragma unroll
    for (int ni = 0; ni < 8; ni++) {
        const int n = ncol0 + ni * 8;
        const float2 b2 = *(const float2*)(bias + n);
#pragma unroll
        for (int mi = 0; mi < 2; mi++) {
            const int m = mrow0 + mi * 16;
            float2 o0 = make_float2(acc[mi][ni][0] + b2.x, acc[mi][ni][1] + b2.y);
            float2 o1 = make_float2(acc[mi][ni][2] + b2.x, acc[mi][ni][3] + b2.y);
            *(float2*)(C + (size_t)m * N + n)       = o0;
            *(float2*)(C + (size_t)(m + 8) * N + n) = o1;
        }
    }
}

// =====================================================================
// Attention: one block per (window, head). 256 threads. (unchanged)
// =====================================================================
__global__ __launch_bounds__(256) void attn_kernel(
    const float* __restrict__ mask, const float* __restrict__ rpb)
{
    const int w = blockIdx.x;
    const int h = blockIdx.y;

    __shared__ float sq  [49 * 36];
    __shared__ float sk  [49 * 36];
    __shared__ float sv  [49 * 32];
    __shared__ float svs [49 * 32];
    __shared__ float svsh[49 * 32];
    __shared__ float sattn[49 * 49];
    __shared__ float srpb[169];

    const int tid = threadIdx.x;

    const float* qbase = g_qkv + (size_t)w * 49 * 1152 + h * 32;
    const float* vsb   = g_vs  + (size_t)w * 49 * 384 + h * 32;
    const float* vshb  = g_vsh + (size_t)w * 49 * 384 + h * 32;

    for (int idx = tid; idx < 169; idx += 256)
        srpb[idx] = rpb[idx * 12 + h];

    for (int idx = tid; idx < 49 * 8; idx += 256) {
        int n = idx >> 3;
        int c = (idx & 7) << 2;
        float4 q4 = *(const float4*)(qbase + (size_t)n * 1152 + c);
        float4 k4 = *(const float4*)(qbase + (size_t)n * 1152 + 384 + c);
        float4 v4 = *(const float4*)(qbase + (size_t)n * 1152 + 768 + c);
        float4 s4 = *(const float4*)(vsb  + (size_t)n * 384 + c);
        float4 t4 = *(const float4*)(vshb + (size_t)n * 384 + c);
        *(float4*)&sq  [n * 36 + c] = q4;
        *(float4*)&sk  [n * 36 + c] = k4;
        *(float4*)&sv  [n * 32 + c] = v4;
        *(float4*)&svs [n * 32 + c] = s4;
        *(float4*)&svsh[n * 32 + c] = t4;
    }
    __syncthreads();

    const float* mrow = mask + (size_t)(w & 15) * 2401;
    if (tid < 245) {
        const int j    = tid / 5;
        const int isub = tid - j * 5;
        const int yj = j / 7, xj = j - yj * 7;

        float kr[32];
#pragma unroll
        for (int c = 0; c < 8; c++) {
            float4 k4 = *(const float4*)&sk[j * 36 + c * 4];
            kr[c * 4 + 0] = k4.x; kr[c * 4 + 1] = k4.y;
            kr[c * 4 + 2] = k4.z; kr[c * 4 + 3] = k4.w;
        }

#pragma unroll
        for (int t = 0; t < 10; t++) {
            int i = isub + t * 5;
            if (i < 49) {
                float acc = 0.f;
#pragma unroll
                for (int c = 0; c < 8; c++) {
                    float4 q4 = *(const float4*)&sq[i * 36 + c * 4];
                    acc += q4.x * kr[c * 4 + 0] + q4.y * kr[c * 4 + 1]
                         + q4.z * kr[c * 4 + 2] + q4.w * kr[c * 4 + 3];
                }
                int yi = i / 7, xi = i - yi * 7;
                int ridx = (yi - yj + 6) * 13 + (xi - xj + 6);
                sattn[i * 49 + j] = acc * ATTN_SCALE + srpb[ridx] + mrow[i * 49 + j];
            }
        }
    }
    __syncthreads();

    if (tid < 49) {
        float m = -1e30f;
#pragma unroll
        for (int jj = 0; jj < 49; jj++) m = fmaxf(m, sattn[tid * 49 + jj]);
        float s = 0.f;
#pragma unroll
        for (int jj = 0; jj < 49; jj++) {
            float e = __expf(sattn[tid * 49 + jj] - m);
            sattn[tid * 49 + jj] = e;
            s += e;
        }
        float inv = 1.f / s;
#pragma unroll
        for (int jj = 0; jj < 49; jj++) sattn[tid * 49 + jj] *= inv;
    }
    __syncthreads();

    const size_t obase = (size_t)w * 49 * 384 + h * 32;
    for (int idx = tid; idx < 392; idx += 256) {
        int i  = idx >> 3;
        int d4 = (idx & 7) << 2;
        float4 a0 = make_float4(0.f, 0.f, 0.f, 0.f);
        float4 a1 = a0, a2 = a0;
#pragma unroll
        for (int j = 0; j < 49; j++) {
            float a = sattn[i * 49 + j];
            float4 v4 = *(const float4*)&sv  [j * 32 + d4];
            float4 s4 = *(const float4*)&svs [j * 32 + d4];
            float4 t4 = *(const float4*)&svsh[j * 32 + d4];
            a0.x += a * v4.x; a0.y += a * v4.y; a0.z += a * v4.z; a0.w += a * v4.w;
            a1.x += a * s4.x; a1.y += a * s4.y; a1.z += a * s4.z; a1.w += a * s4.w;
            a2.x += a * t4.x; a2.y += a * t4.y; a2.z += a * t4.z; a2.w += a * t4.w;
        }
        size_t off = obase + (size_t)i * 384 + d4;
        *(float4*)&g_o[off]          = a0;
        *(float4*)&g_o[OS + off]     = a1;
        *(float4*)&g_o[2 * OS + off] = a2;
    }
}

// =====================================================================
// launch
// =====================================================================
extern "C" void kernel_launch(void* const* d_in, const int* in_sizes, int n_in,
                              void* d_out, int out_size)
{
    (void)in_sizes; (void)n_in; (void)out_size;

    const float* x            = (const float*)d_in[0];
    const float* scale        = (const float*)d_in[1];
    const float* shift        = (const float*)d_in[2];
    const float* mask         = (const float*)d_in[3];
    const float* qkv_w        = (const float*)d_in[4];
    const float* qkv_b        = (const float*)d_in[5];
    const float* vscale_w     = (const float*)d_in[6];
    const float* vscale_b     = (const float*)d_in[7];
    const float* vshift_w     = (const float*)d_in[8];
    const float* vshift_b     = (const float*)d_in[9];
    const float* rpb_table    = (const float*)d_in[10];
    const float* proj_x_w     = (const float*)d_in[11];
    const float* proj_x_b     = (const float*)d_in[12];
    const float* proj_scale_w = (const float*)d_in[13];
    const float* proj_scale_b = (const float*)d_in[14];
    const float* proj_shift_w = (const float*)d_in[15];
    const float* proj_shift_b = (const float*)d_in[16];
    float* out = (float*)d_out;

    float *p_qkv, *p_vs, *p_vsh, *p_o;
    cudaGetSymbolAddress((void**)&p_qkv, g_qkv);
    cudaGetSymbolAddress((void**)&p_vs,  g_vs);
    cudaGetSymbolAddress((void**)&p_vsh, g_vsh);
    cudaGetSymbolAddress((void**)&p_o,   g_o);

    cudaFuncSetAttribute(gemm_mma_kernel,
                         cudaFuncAttributeMaxDynamicSharedMemorySize, GEMM_SMEM_BYTES);

    const int gridM = MROWS / 128;   // 392
    dim3 blk(256);
    dim3 gq(1152 / 128, gridM);
    dim3 g3(384 / 128, gridM);

    gemm_mma_kernel<<<gq, blk, GEMM_SMEM_BYTES>>>(x,     qkv_w,    qkv_b,    p_qkv, 1152);
    gemm_mma_kernel<<<g3, blk, GEMM_SMEM_BYTES>>>(scale, vscale_w, vscale_b, p_vs,  384);
    gemm_mma_kernel<<<g3, blk, GEMM_SMEM_BYTES>>>(shift, vshift_w, vshift_b, p_vsh, 384);

    dim3 agrid(BW, NHEAD);
    attn_kernel<<<agrid, 256>>>(mask, rpb_table);

    gemm_mma_kernel<<<g3, blk, GEMM_SMEM_BYTES>>>(p_o,          proj_x_w,     proj_x_b,     out,          384);
    gemm_mma_kernel<<<g3, blk, GEMM_SMEM_BYTES>>>(p_o + OS,     proj_scale_w, proj_scale_b, out + OS,     384);
    gemm_mma_kernel<<<g3, blk, GEMM_SMEM_BYTES>>>(p_o + 2 * OS, proj_shift_w, proj_shift_b, out + 2 * OS, 384);
}

// round 4
// speedup vs baseline: 1.4368x; 1.1019x over previous
#include <cuda_runtime.h>
#include <cuda_bf16.h>
#include <cstdint>

// ---------------- problem constants ----------------
#define BW     1024
#define NTOK   49
#define CDIM   384
#define NHEAD  12
#define MROWS  (BW * NTOK)   // 50176
#define OS     19267584      // 50176*384
#define ATTN_SCALE 0.17677669529663687f

// ---------------- scratch (device globals) ----------------
__device__ float g_qkv[57802752];                 // [50176,1152] fp32 (attn input)
__device__ float g_vs [19267584];                 // fp32
__device__ float g_vsh[19267584];                 // fp32
__device__ __nv_bfloat16 g_xhi[19267584], g_xlo[19267584];
__device__ __nv_bfloat16 g_schi[19267584], g_sclo[19267584];
__device__ __nv_bfloat16 g_shhi[19267584], g_shlo[19267584];
__device__ __nv_bfloat16 g_ohi[57802752], g_olo[57802752];   // attn out, 3 streams
__device__ __nv_bfloat16 g_whi[1179648],  g_wlo[1179648];    // all weights hi/lo
// weight offsets in g_whi/g_wlo
#define WOFF_QKV  0
#define WOFF_VS   442368
#define WOFF_VSH  589824
#define WOFF_PX   737280
#define WOFF_PS   884736
#define WOFF_PSH  1032192

// =====================================================================
// helpers
// =====================================================================
__device__ __forceinline__ uint32_t smem_u32(const void* p) {
    uint32_t a;
    asm("{ .reg .u64 t; cvta.to.shared.u64 t, %1; cvt.u32.u64 %0, t; }" : "=r"(a) : "l"(p));
    return a;
}
__device__ __forceinline__ void ldsm_x4(uint32_t* r, uint32_t addr) {
    asm volatile("ldmatrix.sync.aligned.m8n8.x4.shared.b16 {%0,%1,%2,%3}, [%4];"
        : "=r"(r[0]), "=r"(r[1]), "=r"(r[2]), "=r"(r[3]) : "r"(addr));
}
__device__ __forceinline__ void ldsm_x4t(uint32_t* r, uint32_t addr) {
    asm volatile("ldmatrix.sync.aligned.m8n8.x4.trans.shared.b16 {%0,%1,%2,%3}, [%4];"
        : "=r"(r[0]), "=r"(r[1]), "=r"(r[2]), "=r"(r[3]) : "r"(addr));
}
__device__ __forceinline__ void mma16816(float* d, const uint32_t* a, const uint32_t* b) {
    asm volatile("mma.sync.aligned.m16n8k16.row.col.f32.bf16.bf16.f32 "
        "{%0,%1,%2,%3}, {%4,%5,%6,%7}, {%8,%9}, {%0,%1,%2,%3};"
        : "+f"(d[0]), "+f"(d[1]), "+f"(d[2]), "+f"(d[3])
        : "r"(a[0]), "r"(a[1]), "r"(a[2]), "r"(a[3]), "r"(b[0]), "r"(b[1]));
}
#define CP_ASYNC16(dst, src) asm volatile("cp.async.cg.shared.global [%0], [%1], 16;" :: "r"(dst), "l"(src))
#define CP_COMMIT()          asm volatile("cp.async.commit_group;" ::: "memory")
#define CP_WAIT(n)           asm volatile("cp.async.wait_group %0;" :: "n"(n) : "memory")

__device__ __forceinline__ void split2(float x, float y, uint32_t& hi, uint32_t& lo) {
    __nv_bfloat16 hx = __float2bfloat16(x);
    __nv_bfloat16 hy = __float2bfloat16(y);
    __nv_bfloat162 hp = __halves2bfloat162(hx, hy);
    __nv_bfloat162 lp = __halves2bfloat162(__float2bfloat16(x - __bfloat162float(hx)),
                                           __float2bfloat16(y - __bfloat162float(hy)));
    hi = *(uint32_t*)&hp;
    lo = *(uint32_t*)&lp;
}

// =====================================================================
// convert fp32 -> bf16 hi/lo (vectorized by 4)
// =====================================================================
__global__ void __launch_bounds__(256) cvt_kernel(
    const float* __restrict__ src, __nv_bfloat16* __restrict__ hi,
    __nv_bfloat16* __restrict__ lo, int n4)
{
    int i = blockIdx.x * 256 + threadIdx.x;
    if (i >= n4) return;
    float4 v = ((const float4*)src)[i];
    uint32_t h0, l0, h1, l1;
    split2(v.x, v.y, h0, l0);
    split2(v.z, v.w, h1, l1);
    ((uint2*)hi)[i] = make_uint2(h0, h1);
    ((uint2*)lo)[i] = make_uint2(l0, l1);
}

// ---------------- smem layout (bytes, per stage) ----------------
// AsHi [128][40]bf16=10240 ; AsLo +10240 ; BsHi [32][136]bf16=8704 ; BsLo +8704
#define AS_HI   0
#define AS_LO   10240
#define BS_HI   20480
#define BS_LO   29184
#define STAGE_B 37888
#define GEMM_SMEM_BYTES (2 * STAGE_B)

// =====================================================================
// bf16x3 tensor-core GEMM: C[M,N] = (Ahi+Alo)(Whi+Wlo) + bias (drop lo*lo)
// grid=(N/128, M/128), 256 thr, K=384, cp.async double buffer.
// =====================================================================
__global__ void __launch_bounds__(256, 2) gemm_mma_kernel(
    const __nv_bfloat16* __restrict__ Ahi, const __nv_bfloat16* __restrict__ Alo,
    const __nv_bfloat16* __restrict__ Whi, const __nv_bfloat16* __restrict__ Wlo,
    const float* __restrict__ bias, float* __restrict__ C, int N)
{
    extern __shared__ char sm[];
    const uint32_t sb = smem_u32(sm);

    const int tid  = threadIdx.x;
    const int lane = tid & 31;
    const int wid  = tid >> 5;
    const int wm   = wid >> 1;       // 0..3
    const int wn   = wid & 1;        // 0..1
    const int bm   = blockIdx.y << 7;
    const int bn   = blockIdx.x << 7;

    // staging indices
    const int arow = tid >> 2;              // reused with +64 for rep 1
    const int aq   = tid & 3;
    const int brow = tid >> 4;              // +16 for rep 1
    const int bq   = tid & 15;

    // fragment addresses
    const uint32_t aoff  = (uint32_t)(((wm * 32 + (lane & 15)) * 40 + ((lane >> 4) << 3)) << 1);
    const uint32_t boff4 = (uint32_t)(((lane & 15) * 136 + wn * 64 + ((lane >> 4) << 3)) << 1);

    float acc[2][8][4];
#pragma unroll
    for (int mi = 0; mi < 2; mi++)
#pragma unroll
        for (int ni = 0; ni < 8; ni++)
#pragma unroll
            for (int r = 0; r < 4; r++) acc[mi][ni][r] = 0.f;

#define ISSUE_STAGE(kc, s) do { \
    const uint32_t std_ = sb + (uint32_t)(s) * STAGE_B; \
    _Pragma("unroll") \
    for (int rep = 0; rep < 2; rep++) { \
        int ar = arow + rep * 64; \
        size_t asrc = (size_t)(bm + ar) * CDIM + (kc) * 32 + aq * 8; \
        uint32_t adst = std_ + ar * 80 + aq * 16; \
        CP_ASYNC16(adst + AS_HI, Ahi + asrc); \
        CP_ASYNC16(adst + AS_LO, Alo + asrc); \
        int br = brow + rep * 16; \
        size_t bsrc = (size_t)((kc) * 32 + br) * N + bn + bq * 8; \
        uint32_t bdst = std_ + br * 272 + bq * 16; \
        CP_ASYNC16(bdst + BS_HI, Whi + bsrc); \
        CP_ASYNC16(bdst + BS_LO, Wlo + bsrc); \
    } \
} while (0)

    ISSUE_STAGE(0, 0);
    CP_COMMIT();

    const int NCHUNK = CDIM / 32;   // 12
#pragma unroll 1
    for (int kc = 0; kc < NCHUNK; kc++) {
        if (kc + 1 < NCHUNK) {
            ISSUE_STAGE(kc + 1, (kc + 1) & 1);
            CP_COMMIT();
            CP_WAIT(1);
        } else {
            CP_WAIT(0);
        }
        __syncthreads();

        const uint32_t st = sb + (uint32_t)(kc & 1) * STAGE_B;
#pragma unroll
        for (int ks = 0; ks < 2; ks++) {
            uint32_t ah[2][4], al[2][4];
            ldsm_x4(ah[0], st + AS_HI + aoff + ks * 32);
            ldsm_x4(ah[1], st + AS_HI + aoff + ks * 32 + 16 * 80);
            ldsm_x4(al[0], st + AS_LO + aoff + ks * 32);
            ldsm_x4(al[1], st + AS_LO + aoff + ks * 32 + 16 * 80);
            const uint32_t bbase = st + boff4 + (uint32_t)(ks * 16 * 272);
#pragma unroll
            for (int np = 0; np < 4; np++) {
                uint32_t bh[4], bl[4];
                ldsm_x4t(bh, bbase + BS_HI + np * 32);
                ldsm_x4t(bl, bbase + BS_LO + np * 32);
                const int n0 = np * 2, n1 = np * 2 + 1;
                mma16816(acc[0][n0], ah[0], bh);
                mma16816(acc[1][n0], ah[1], bh);
                mma16816(acc[0][n0], al[0], bh);
                mma16816(acc[1][n0], al[1], bh);
                mma16816(acc[0][n0], ah[0], bl);
                mma16816(acc[1][n0], ah[1], bl);
                mma16816(acc[0][n1], ah[0], bh + 2);
                mma16816(acc[1][n1], ah[1], bh + 2);
                mma16816(acc[0][n1], al[0], bh + 2);
                mma16816(acc[1][n1], al[1], bh + 2);
                mma16816(acc[0][n1], ah[0], bl + 2);
                mma16816(acc[1][n1], ah[1], bl + 2);
            }
        }
        __syncthreads();
    }

    // ---- epilogue ----
    const int mrow0 = bm + wm * 32 + (lane >> 2);
    const int ncol0 = bn + wn * 64 + ((lane & 3) << 1);
#pragma unroll
    for (int ni = 0; ni < 8; ni++) {
        const int n = ncol0 + ni * 8;
        const float2 b2 = *(const float2*)(bias + n);
#pragma unroll
        for (int mi = 0; mi < 2; mi++) {
            const int m = mrow0 + mi * 16;
            *(float2*)(C + (size_t)m * N + n) =
                make_float2(acc[mi][ni][0] + b2.x, acc[mi][ni][1] + b2.y);
            *(float2*)(C + (size_t)(m + 8) * N + n) =
                make_float2(acc[mi][ni][2] + b2.x, acc[mi][ni][3] + b2.y);
        }
    }
}

// =====================================================================
// Attention: block per (window, head). Writes bf16 hi/lo outputs.
// =====================================================================
__global__ __launch_bounds__(256) void attn_kernel(
    const float* __restrict__ mask, const float* __restrict__ rpb)
{
    const int w = blockIdx.x;
    const int h = blockIdx.y;

    __shared__ float sq  [49 * 36];
    __shared__ float sk  [49 * 36];
    __shared__ float sv  [49 * 32];
    __shared__ float svs [49 * 32];
    __shared__ float svsh[49 * 32];
    __shared__ float sattn[49 * 49];
    __shared__ float srpb[169];

    const int tid = threadIdx.x;

    const float* qbase = g_qkv + (size_t)w * 49 * 1152 + h * 32;
    const float* vsb   = g_vs  + (size_t)w * 49 * 384 + h * 32;
    const float* vshb  = g_vsh + (size_t)w * 49 * 384 + h * 32;

    for (int idx = tid; idx < 169; idx += 256)
        srpb[idx] = rpb[idx * 12 + h];

    for (int idx = tid; idx < 49 * 8; idx += 256) {
        int n = idx >> 3;
        int c = (idx & 7) << 2;
        float4 q4 = *(const float4*)(qbase + (size_t)n * 1152 + c);
        float4 k4 = *(const float4*)(qbase + (size_t)n * 1152 + 384 + c);
        float4 v4 = *(const float4*)(qbase + (size_t)n * 1152 + 768 + c);
        float4 s4 = *(const float4*)(vsb  + (size_t)n * 384 + c);
        float4 t4 = *(const float4*)(vshb + (size_t)n * 384 + c);
        *(float4*)&sq  [n * 36 + c] = q4;
        *(float4*)&sk  [n * 36 + c] = k4;
        *(float4*)&sv  [n * 32 + c] = v4;
        *(float4*)&svs [n * 32 + c] = s4;
        *(float4*)&svsh[n * 32 + c] = t4;
    }
    __syncthreads();

    const float* mrow = mask + (size_t)(w & 15) * 2401;
    if (tid < 245) {
        const int j    = tid / 5;
        const int isub = tid - j * 5;
        const int yj = j / 7, xj = j - yj * 7;

        float kr[32];
#pragma unroll
        for (int c = 0; c < 8; c++) {
            float4 k4 = *(const float4*)&sk[j * 36 + c * 4];
            kr[c * 4 + 0] = k4.x; kr[c * 4 + 1] = k4.y;
            kr[c * 4 + 2] = k4.z; kr[c * 4 + 3] = k4.w;
        }
#pragma unroll
        for (int t = 0; t < 10; t++) {
            int i = isub + t * 5;
            if (i < 49) {
                float acc = 0.f;
#pragma unroll
                for (int c = 0; c < 8; c++) {
                    float4 q4 = *(const float4*)&sq[i * 36 + c * 4];
                    acc += q4.x * kr[c * 4 + 0] + q4.y * kr[c * 4 + 1]
                         + q4.z * kr[c * 4 + 2] + q4.w * kr[c * 4 + 3];
                }
                int yi = i / 7, xi = i - yi * 7;
                int ridx = (yi - yj + 6) * 13 + (xi - xj + 6);
                sattn[i * 49 + j] = acc * ATTN_SCALE + srpb[ridx] + mrow[i * 49 + j];
            }
        }
    }
    __syncthreads();

    if (tid < 49) {
        float m = -1e30f;
#pragma unroll
        for (int jj = 0; jj < 49; jj++) m = fmaxf(m, sattn[tid * 49 + jj]);
        float s = 0.f;
#pragma unroll
        for (int jj = 0; jj < 49; jj++) {
            float e = __expf(sattn[tid * 49 + jj] - m);
            sattn[tid * 49 + jj] = e;
            s += e;
        }
        float inv = 1.f / s;
#pragma unroll
        for (int jj = 0; jj < 49; jj++) sattn[tid * 49 + jj] *= inv;
    }
    __syncthreads();

    const size_t obase = (size_t)w * 49 * 384 + h * 32;
    for (int idx = tid; idx < 392; idx += 256) {
        int i  = idx >> 3;
        int d4 = (idx & 7) << 2;
        float4 a0 = make_float4(0.f, 0.f, 0.f, 0.f);
        float4 a1 = a0, a2 = a0;
#pragma unroll
        for (int j = 0; j < 49; j++) {
            float a = sattn[i * 49 + j];
            float4 v4 = *(const float4*)&sv  [j * 32 + d4];
            float4 s4 = *(const float4*)&svs [j * 32 + d4];
            float4 t4 = *(const float4*)&svsh[j * 32 + d4];
            a0.x += a * v4.x; a0.y += a * v4.y; a0.z += a * v4.z; a0.w += a * v4.w;
            a1.x += a * s4.x; a1.y += a * s4.y; a1.z += a * s4.z; a1.w += a * s4.w;
            a2.x += a * t4.x; a2.y += a * t4.y; a2.z += a * t4.z; a2.w += a * t4.w;
        }
        size_t off = obase + (size_t)i * 384 + d4;
        uint32_t h0, l0, h1, l1;
        split2(a0.x, a0.y, h0, l0); split2(a0.z, a0.w, h1, l1);
        *(uint2*)&g_ohi[off] = make_uint2(h0, h1);
        *(uint2*)&g_olo[off] = make_uint2(l0, l1);
        split2(a1.x, a1.y, h0, l0); split2(a1.z, a1.w, h1, l1);
        *(uint2*)&g_ohi[OS + off] = make_uint2(h0, h1);
        *(uint2*)&g_olo[OS + off] = make_uint2(l0, l1);
        split2(a2.x, a2.y, h0, l0); split2(a2.z, a2.w, h1, l1);
        *(uint2*)&g_ohi[2 * OS + off] = make_uint2(h0, h1);
        *(uint2*)&g_olo[2 * OS + off] = make_uint2(l0, l1);
    }
}

// =====================================================================
// launch
// =====================================================================
extern "C" void kernel_launch(void* const* d_in, const int* in_sizes, int n_in,
                              void* d_out, int out_size)
{
    (void)in_sizes; (void)n_in; (void)out_size;

    const float* x            = (const float*)d_in[0];
    const float* scale        = (const float*)d_in[1];
    const float* shift        = (const float*)d_in[2];
    const float* mask         = (const float*)d_in[3];
    const float* qkv_w        = (const float*)d_in[4];
    const float* qkv_b        = (const float*)d_in[5];
    const float* vscale_w     = (const float*)d_in[6];
    const float* vscale_b     = (const float*)d_in[7];
    const float* vshift_w     = (const float*)d_in[8];
    const float* vshift_b     = (const float*)d_in[9];
    const float* rpb_table    = (const float*)d_in[10];
    const float* proj_x_w     = (const float*)d_in[11];
    const float* proj_x_b     = (const float*)d_in[12];
    const float* proj_scale_w = (const float*)d_in[13];
    const float* proj_scale_b = (const float*)d_in[14];
    const float* proj_shift_w = (const float*)d_in[15];
    const float* proj_shift_b = (const float*)d_in[16];
    float* out = (float*)d_out;

    float *p_qkv, *p_vs, *p_vsh;
    __nv_bfloat16 *p_xhi, *p_xlo, *p_schi, *p_sclo, *p_shhi, *p_shlo;
    __nv_bfloat16 *p_ohi, *p_olo, *p_whi, *p_wlo;
    cudaGetSymbolAddress((void**)&p_qkv, g_qkv);
    cudaGetSymbolAddress((void**)&p_vs,  g_vs);
    cudaGetSymbolAddress((void**)&p_vsh, g_vsh);
    cudaGetSymbolAddress((void**)&p_xhi, g_xhi);
    cudaGetSymbolAddress((void**)&p_xlo, g_xlo);
    cudaGetSymbolAddress((void**)&p_schi, g_schi);
    cudaGetSymbolAddress((void**)&p_sclo, g_sclo);
    cudaGetSymbolAddress((void**)&p_shhi, g_shhi);
    cudaGetSymbolAddress((void**)&p_shlo, g_shlo);
    cudaGetSymbolAddress((void**)&p_ohi, g_ohi);
    cudaGetSymbolAddress((void**)&p_olo, g_olo);
    cudaGetSymbolAddress((void**)&p_whi, g_whi);
    cudaGetSymbolAddress((void**)&p_wlo, g_wlo);

    cudaFuncSetAttribute(gemm_mma_kernel,
                         cudaFuncAttributeMaxDynamicSharedMemorySize, GEMM_SMEM_BYTES);

    // ---- one-time conversions (cheap) ----
    cvt_kernel<<<(442368 / 4 + 255) / 256, 256>>>(qkv_w,        p_whi + WOFF_QKV, p_wlo + WOFF_QKV, 442368 / 4);
    cvt_kernel<<<(147456 / 4 + 255) / 256, 256>>>(vscale_w,     p_whi + WOFF_VS,  p_wlo + WOFF_VS,  147456 / 4);
    cvt_kernel<<<(147456 / 4 + 255) / 256, 256>>>(vshift_w,     p_whi + WOFF_VSH, p_wlo + WOFF_VSH, 147456 / 4);
    cvt_kernel<<<(147456 / 4 + 255) / 256, 256>>>(proj_x_w,     p_whi + WOFF_PX,  p_wlo + WOFF_PX,  147456 / 4);
    cvt_kernel<<<(147456 / 4 + 255) / 256, 256>>>(proj_scale_w, p_whi + WOFF_PS,  p_wlo + WOFF_PS,  147456 / 4);
    cvt_kernel<<<(147456 / 4 + 255) / 256, 256>>>(proj_shift_w, p_whi + WOFF_PSH, p_wlo + WOFF_PSH, 147456 / 4);
    cvt_kernel<<<(OS / 4 + 255) / 256, 256>>>(x,     p_xhi,  p_xlo,  OS / 4);
    cvt_kernel<<<(OS / 4 + 255) / 256, 256>>>(scale, p_schi, p_sclo, OS / 4);
    cvt_kernel<<<(OS / 4 + 255) / 256, 256>>>(shift, p_shhi, p_shlo, OS / 4);

    const int gridM = MROWS / 128;   // 392
    dim3 blk(256);
    dim3 gq(1152 / 128, gridM);
    dim3 g3(384 / 128, gridM);

    gemm_mma_kernel<<<gq, blk, GEMM_SMEM_BYTES>>>(p_xhi,  p_xlo,  p_whi + WOFF_QKV, p_wlo + WOFF_QKV, qkv_b,    p_qkv, 1152);
    gemm_mma_kernel<<<g3, blk, GEMM_SMEM_BYTES>>>(p_schi, p_sclo, p_whi + WOFF_VS,  p_wlo + WOFF_VS,  vscale_b, p_vs,  384);
    gemm_mma_kernel<<<g3, blk, GEMM_SMEM_BYTES>>>(p_shhi, p_shlo, p_whi + WOFF_VSH, p_wlo + WOFF_VSH, vshift_b, p_vsh, 384);

    dim3 agrid(BW, NHEAD);
    attn_kernel<<<agrid, 256>>>(mask, rpb_table);

    gemm_mma_kernel<<<g3, blk, GEMM_SMEM_BYTES>>>(p_ohi,          p_olo,          p_whi + WOFF_PX,  p_wlo + WOFF_PX,  proj_x_b,     out,          384);
    gemm_mma_kernel<<<g3, blk, GEMM_SMEM_BYTES>>>(p_ohi + OS,     p_olo + OS,     p_whi + WOFF_PS,  p_wlo + WOFF_PS,  proj_scale_b, out + OS,     384);
    gemm_mma_kernel<<<g3, blk, GEMM_SMEM_BYTES>>>(p_ohi + 2 * OS, p_olo + 2 * OS, p_whi + WOFF_PSH, p_wlo + WOFF_PSH, proj_shift_b, out + 2 * OS, 384);
}

// round 5
// speedup vs baseline: 1.5553x; 1.0825x over previous
#include <cuda_runtime.h>
#include <cuda_fp16.h>
#include <cstdint>

// ---------------- problem constants ----------------
#define BW     1024
#define NTOK   49
#define CDIM   384
#define NHEAD  12
#define MROWS  (BW * NTOK)   // 50176
#define OS     19267584      // 50176*384
#define ATTN_SCALE 0.17677669529663687f

// ---------------- scratch (device globals) ----------------
__device__ float g_qkv[57802752];                 // [50176,1152] fp32 (attn input)
__device__ float g_vs [19267584];
__device__ float g_vsh[19267584];
__device__ __half g_xhi[19267584],  g_xlo[19267584];
__device__ __half g_schi[19267584], g_sclo[19267584];
__device__ __half g_shhi[19267584], g_shlo[19267584];
__device__ __half g_ohi[57802752],  g_olo[57802752];   // attn out, 3 streams
__device__ __half g_whi[1179648];                       // all weights (hi only)
#define WOFF_QKV  0
#define WOFF_VS   442368
#define WOFF_VSH  589824
#define WOFF_PX   737280
#define WOFF_PS   884736
#define WOFF_PSH  1032192

// =====================================================================
// helpers
// =====================================================================
__device__ __forceinline__ uint32_t smem_u32(const void* p) {
    uint32_t a;
    asm("{ .reg .u64 t; cvta.to.shared.u64 t, %1; cvt.u32.u64 %0, t; }" : "=r"(a) : "l"(p));
    return a;
}
__device__ __forceinline__ void ldsm_x4(uint32_t* r, uint32_t addr) {
    asm volatile("ldmatrix.sync.aligned.m8n8.x4.shared.b16 {%0,%1,%2,%3}, [%4];"
        : "=r"(r[0]), "=r"(r[1]), "=r"(r[2]), "=r"(r[3]) : "r"(addr));
}
__device__ __forceinline__ void ldsm_x4t(uint32_t* r, uint32_t addr) {
    asm volatile("ldmatrix.sync.aligned.m8n8.x4.trans.shared.b16 {%0,%1,%2,%3}, [%4];"
        : "=r"(r[0]), "=r"(r[1]), "=r"(r[2]), "=r"(r[3]) : "r"(addr));
}
__device__ __forceinline__ void mma16816(float* d, const uint32_t* a, const uint32_t* b) {
    asm volatile("mma.sync.aligned.m16n8k16.row.col.f32.f16.f16.f32 "
        "{%0,%1,%2,%3}, {%4,%5,%6,%7}, {%8,%9}, {%0,%1,%2,%3};"
        : "+f"(d[0]), "+f"(d[1]), "+f"(d[2]), "+f"(d[3])
        : "r"(a[0]), "r"(a[1]), "r"(a[2]), "r"(a[3]), "r"(b[0]), "r"(b[1]));
}
#define CP_ASYNC16(dst, src) asm volatile("cp.async.cg.shared.global [%0], [%1], 16;" :: "r"(dst), "l"(src))
#define CP_COMMIT()          asm volatile("cp.async.commit_group;" ::: "memory")
#define CP_WAIT(n)           asm volatile("cp.async.wait_group %0;" :: "n"(n) : "memory")

// fp16 hi/lo split of 2 floats
__device__ __forceinline__ void split2h(float x, float y, uint32_t& hi, uint32_t& lo) {
    __half hx = __float2half_rn(x);
    __half hy = __float2half_rn(y);
    __half2 hp = __halves2half2(hx, hy);
    __half2 lp = __halves2half2(__float2half_rn(x - __half2float(hx)),
                                __float2half_rn(y - __half2float(hy)));
    hi = *(uint32_t*)&hp;
    lo = *(uint32_t*)&lp;
}

// =====================================================================
// convert fp32 -> fp16 hi/lo (activations)
// =====================================================================
__global__ void __launch_bounds__(256) cvt_kernel(
    const float* __restrict__ src, __half* __restrict__ hi,
    __half* __restrict__ lo, int n4)
{
    int i = blockIdx.x * 256 + threadIdx.x;
    if (i >= n4) return;
    float4 v = ((const float4*)src)[i];
    uint32_t h0, l0, h1, l1;
    split2h(v.x, v.y, h0, l0);
    split2h(v.z, v.w, h1, l1);
    ((uint2*)hi)[i] = make_uint2(h0, h1);
    ((uint2*)lo)[i] = make_uint2(l0, l1);
}

// all 6 weight tensors -> fp16 hi (single launch)
__global__ void __launch_bounds__(256) cvt_w_kernel(
    const float* __restrict__ w0, const float* __restrict__ w1,
    const float* __restrict__ w2, const float* __restrict__ w3,
    const float* __restrict__ w4, const float* __restrict__ w5,
    __half* __restrict__ hi)
{
    int i = blockIdx.x * 256 + threadIdx.x;     // float4 index, total 294912
    if (i >= 294912) return;
    const float* src;
    int k;
    if (i < 110592) { src = w0; k = i; }
    else {
        int j = i - 110592;
        int seg = j / 36864;
        k = j - seg * 36864;
        src = (seg == 0) ? w1 : (seg == 1) ? w2 : (seg == 2) ? w3 : (seg == 3) ? w4 : w5;
    }
    float4 v = ((const float4*)src)[k];
    __half2 a = __floats2half2_rn(v.x, v.y);
    __half2 b = __floats2half2_rn(v.z, v.w);
    ((uint2*)hi)[i] = make_uint2(*(uint32_t*)&a, *(uint32_t*)&b);
}

// ---------------- smem layout (bytes, per stage) ----------------
// AsHi [128][40]h=10240 ; AsLo +10240 ; BsHi [32][136]h=8704
#define AS_HI   0
#define AS_LO   10240
#define BS_HI   20480
#define STAGE_B 29184
#define NSTAGE  3
#define GEMM_SMEM_BYTES (NSTAGE * STAGE_B)

// =====================================================================
// fp16 2-term tensor-core GEMM: C[M,N] = (Ahi+Alo) @ Whi + bias
// grid=(N/128, M/128), 256 thr, K=384, 3-stage cp.async pipeline.
// =====================================================================
__global__ void __launch_bounds__(256, 2) gemm_mma_kernel(
    const __half* __restrict__ Ahi, const __half* __restrict__ Alo,
    const __half* __restrict__ Whi,
    const float* __restrict__ bias, float* __restrict__ C, int N)
{
    extern __shared__ char sm[];
    const uint32_t sb = smem_u32(sm);

    const int tid  = threadIdx.x;
    const int lane = tid & 31;
    const int wid  = tid >> 5;
    const int wm   = wid >> 1;       // 0..3
    const int wn   = wid & 1;        // 0..1
    const int bm   = blockIdx.y << 7;
    const int bn   = blockIdx.x << 7;

    const int arow = tid >> 2;
    const int aq   = tid & 3;
    const int brow = tid >> 4;
    const int bq   = tid & 15;

    const uint32_t aoff  = (uint32_t)(((wm * 32 + (lane & 15)) * 40 + ((lane >> 4) << 3)) << 1);
    const uint32_t boff4 = (uint32_t)(((lane & 15) * 136 + wn * 64 + ((lane >> 4) << 3)) << 1);

    float acc[2][8][4];
#pragma unroll
    for (int mi = 0; mi < 2; mi++)
#pragma unroll
        for (int ni = 0; ni < 8; ni++)
#pragma unroll
            for (int r = 0; r < 4; r++) acc[mi][ni][r] = 0.f;

#define ISSUE_STAGE(kc, s) do { \
    const uint32_t std_ = sb + (uint32_t)(s) * STAGE_B; \
    _Pragma("unroll") \
    for (int rep = 0; rep < 2; rep++) { \
        int ar = arow + rep * 64; \
        size_t asrc = (size_t)(bm + ar) * CDIM + (kc) * 32 + aq * 8; \
        uint32_t adst = std_ + ar * 80 + aq * 16; \
        CP_ASYNC16(adst + AS_HI, Ahi + asrc); \
        CP_ASYNC16(adst + AS_LO, Alo + asrc); \
        int br = brow + rep * 16; \
        size_t bsrc = (size_t)((kc) * 32 + br) * N + bn + bq * 8; \
        CP_ASYNC16(std_ + BS_HI + br * 272 + bq * 16, Whi + bsrc); \
    } \
} while (0)

    ISSUE_STAGE(0, 0); CP_COMMIT();
    ISSUE_STAGE(1, 1); CP_COMMIT();

    const int NCHUNK = CDIM / 32;   // 12
#pragma unroll 1
    for (int kc = 0; kc < NCHUNK; kc++) {
        if (kc == NCHUNK - 1) { CP_WAIT(0); } else { CP_WAIT(1); }
        __syncthreads();
        if (kc + 2 < NCHUNK) {
            int s2 = (kc + 2) % NSTAGE;
            ISSUE_STAGE(kc + 2, s2);
            CP_COMMIT();
        }

        const uint32_t st = sb + (uint32_t)(kc % NSTAGE) * STAGE_B;
#pragma unroll
        for (int ks = 0; ks < 2; ks++) {
            uint32_t ah[2][4], al[2][4];
            ldsm_x4(ah[0], st + AS_HI + aoff + ks * 32);
            ldsm_x4(ah[1], st + AS_HI + aoff + ks * 32 + 16 * 80);
            ldsm_x4(al[0], st + AS_LO + aoff + ks * 32);
            ldsm_x4(al[1], st + AS_LO + aoff + ks * 32 + 16 * 80);
            const uint32_t bbase = st + BS_HI + boff4 + (uint32_t)(ks * 16 * 272);
#pragma unroll
            for (int np = 0; np < 4; np++) {
                uint32_t bh[4];
                ldsm_x4t(bh, bbase + np * 32);
                const int n0 = np * 2, n1 = np * 2 + 1;
                mma16816(acc[0][n0], ah[0], bh);
                mma16816(acc[1][n0], ah[1], bh);
                mma16816(acc[0][n0], al[0], bh);
                mma16816(acc[1][n0], al[1], bh);
                mma16816(acc[0][n1], ah[0], bh + 2);
                mma16816(acc[1][n1], ah[1], bh + 2);
                mma16816(acc[0][n1], al[0], bh + 2);
                mma16816(acc[1][n1], al[1], bh + 2);
            }
        }
    }

    // ---- epilogue ----
    const int mrow0 = bm + wm * 32 + (lane >> 2);
    const int ncol0 = bn + wn * 64 + ((lane & 3) << 1);
#pragma unroll
    for (int ni = 0; ni < 8; ni++) {
        const int n = ncol0 + ni * 8;
        const float2 b2 = *(const float2*)(bias + n);
#pragma unroll
        for (int mi = 0; mi < 2; mi++) {
            const int m = mrow0 + mi * 16;
            *(float2*)(C + (size_t)m * N + n) =
                make_float2(acc[mi][ni][0] + b2.x, acc[mi][ni][1] + b2.y);
            *(float2*)(C + (size_t)(m + 8) * N + n) =
                make_float2(acc[mi][ni][2] + b2.x, acc[mi][ni][3] + b2.y);
        }
    }
}

// =====================================================================
// Attention: block per (window, head). Writes fp16 hi/lo outputs.
// =====================================================================
__global__ __launch_bounds__(256) void attn_kernel(
    const float* __restrict__ mask, const float* __restrict__ rpb)
{
    const int w = blockIdx.x;
    const int h = blockIdx.y;

    __shared__ float sq  [49 * 36];
    __shared__ float sk  [49 * 36];
    __shared__ float sv  [49 * 32];
    __shared__ float svs [49 * 32];
    __shared__ float svsh[49 * 32];
    __shared__ float sattn[49 * 49];
    __shared__ float srpb[169];

    const int tid = threadIdx.x;

    const float* qbase = g_qkv + (size_t)w * 49 * 1152 + h * 32;
    const float* vsb   = g_vs  + (size_t)w * 49 * 384 + h * 32;
    const float* vshb  = g_vsh + (size_t)w * 49 * 384 + h * 32;

    for (int idx = tid; idx < 169; idx += 256)
        srpb[idx] = rpb[idx * 12 + h];

    for (int idx = tid; idx < 49 * 8; idx += 256) {
        int n = idx >> 3;
        int c = (idx & 7) << 2;
        float4 q4 = *(const float4*)(qbase + (size_t)n * 1152 + c);
        float4 k4 = *(const float4*)(qbase + (size_t)n * 1152 + 384 + c);
        float4 v4 = *(const float4*)(qbase + (size_t)n * 1152 + 768 + c);
        float4 s4 = *(const float4*)(vsb  + (size_t)n * 384 + c);
        float4 t4 = *(const float4*)(vshb + (size_t)n * 384 + c);
        *(float4*)&sq  [n * 36 + c] = q4;
        *(float4*)&sk  [n * 36 + c] = k4;
        *(float4*)&sv  [n * 32 + c] = v4;
        *(float4*)&svs [n * 32 + c] = s4;
        *(float4*)&svsh[n * 32 + c] = t4;
    }
    __syncthreads();

    const float* mrow = mask + (size_t)(w & 15) * 2401;
    if (tid < 245) {
        const int j    = tid / 5;
        const int isub = tid - j * 5;
        const int yj = j / 7, xj = j - yj * 7;

        float kr[32];
#pragma unroll
        for (int c = 0; c < 8; c++) {
            float4 k4 = *(const float4*)&sk[j * 36 + c * 4];
            kr[c * 4 + 0] = k4.x; kr[c * 4 + 1] = k4.y;
            kr[c * 4 + 2] = k4.z; kr[c * 4 + 3] = k4.w;
        }
#pragma unroll
        for (int t = 0; t < 10; t++) {
            int i = isub + t * 5;
            if (i < 49) {
                float acc = 0.f;
#pragma unroll
                for (int c = 0; c < 8; c++) {
                    float4 q4 = *(const float4*)&sq[i * 36 + c * 4];
                    acc += q4.x * kr[c * 4 + 0] + q4.y * kr[c * 4 + 1]
                         + q4.z * kr[c * 4 + 2] + q4.w * kr[c * 4 + 3];
                }
                int yi = i / 7, xi = i - yi * 7;
                int ridx = (yi - yj + 6) * 13 + (xi - xj + 6);
                sattn[i * 49 + j] = acc * ATTN_SCALE + srpb[ridx] + mrow[i * 49 + j];
            }
        }
    }
    __syncthreads();

    if (tid < 49) {
        float m = -1e30f;
#pragma unroll
        for (int jj = 0; jj < 49; jj++) m = fmaxf(m, sattn[tid * 49 + jj]);
        float s = 0.f;
#pragma unroll
        for (int jj = 0; jj < 49; jj++) {
            float e = __expf(sattn[tid * 49 + jj] - m);
            sattn[tid * 49 + jj] = e;
            s += e;
        }
        float inv = 1.f / s;
#pragma unroll
        for (int jj = 0; jj < 49; jj++) sattn[tid * 49 + jj] *= inv;
    }
    __syncthreads();

    const size_t obase = (size_t)w * 49 * 384 + h * 32;
    for (int idx = tid; idx < 392; idx += 256) {
        int i  = idx >> 3;
        int d4 = (idx & 7) << 2;
        float4 a0 = make_float4(0.f, 0.f, 0.f, 0.f);
        float4 a1 = a0, a2 = a0;
#pragma unroll
        for (int j = 0; j < 49; j++) {
            float a = sattn[i * 49 + j];
            float4 v4 = *(const float4*)&sv  [j * 32 + d4];
            float4 s4 = *(const float4*)&svs [j * 32 + d4];
            float4 t4 = *(const float4*)&svsh[j * 32 + d4];
            a0.x += a * v4.x; a0.y += a * v4.y; a0.z += a * v4.z; a0.w += a * v4.w;
            a1.x += a * s4.x; a1.y += a * s4.y; a1.z += a * s4.z; a1.w += a * s4.w;
            a2.x += a * t4.x; a2.y += a * t4.y; a2.z += a * t4.z; a2.w += a * t4.w;
        }
        size_t off = obase + (size_t)i * 384 + d4;
        uint32_t h0, l0, h1, l1;
        split2h(a0.x, a0.y, h0, l0); split2h(a0.z, a0.w, h1, l1);
        *(uint2*)&g_ohi[off] = make_uint2(h0, h1);
        *(uint2*)&g_olo[off] = make_uint2(l0, l1);
        split2h(a1.x, a1.y, h0, l0); split2h(a1.z, a1.w, h1, l1);
        *(uint2*)&g_ohi[OS + off] = make_uint2(h0, h1);
        *(uint2*)&g_olo[OS + off] = make_uint2(l0, l1);
        split2h(a2.x, a2.y, h0, l0); split2h(a2.z, a2.w, h1, l1);
        *(uint2*)&g_ohi[2 * OS + off] = make_uint2(h0, h1);
        *(uint2*)&g_olo[2 * OS + off] = make_uint2(l0, l1);
    }
}

// =====================================================================
// launch
// =====================================================================
extern "C" void kernel_launch(void* const* d_in, const int* in_sizes, int n_in,
                              void* d_out, int out_size)
{
    (void)in_sizes; (void)n_in; (void)out_size;

    const float* x            = (const float*)d_in[0];
    const float* scale        = (const float*)d_in[1];
    const float* shift        = (const float*)d_in[2];
    const float* mask         = (const float*)d_in[3];
    const float* qkv_w        = (const float*)d_in[4];
    const float* qkv_b        = (const float*)d_in[5];
    const float* vscale_w     = (const float*)d_in[6];
    const float* vscale_b     = (const float*)d_in[7];
    const float* vshift_w     = (const float*)d_in[8];
    const float* vshift_b     = (const float*)d_in[9];
    const float* rpb_table    = (const float*)d_in[10];
    const float* proj_x_w     = (const float*)d_in[11];
    const float* proj_x_b     = (const float*)d_in[12];
    const float* proj_scale_w = (const float*)d_in[13];
    const float* proj_scale_b = (const float*)d_in[14];
    const float* proj_shift_w = (const float*)d_in[15];
    const float* proj_shift_b = (const float*)d_in[16];
    float* out = (float*)d_out;

    float *p_qkv, *p_vs, *p_vsh;
    __half *p_xhi, *p_xlo, *p_schi, *p_sclo, *p_shhi, *p_shlo;
    __half *p_ohi, *p_olo, *p_whi;
    cudaGetSymbolAddress((void**)&p_qkv, g_qkv);
    cudaGetSymbolAddress((void**)&p_vs,  g_vs);
    cudaGetSymbolAddress((void**)&p_vsh, g_vsh);
    cudaGetSymbolAddress((void**)&p_xhi, g_xhi);
    cudaGetSymbolAddress((void**)&p_xlo, g_xlo);
    cudaGetSymbolAddress((void**)&p_schi, g_schi);
    cudaGetSymbolAddress((void**)&p_sclo, g_sclo);
    cudaGetSymbolAddress((void**)&p_shhi, g_shhi);
    cudaGetSymbolAddress((void**)&p_shlo, g_shlo);
    cudaGetSymbolAddress((void**)&p_ohi, g_ohi);
    cudaGetSymbolAddress((void**)&p_olo, g_olo);
    cudaGetSymbolAddress((void**)&p_whi, g_whi);

    cudaFuncSetAttribute(gemm_mma_kernel,
                         cudaFuncAttributeMaxDynamicSharedMemorySize, GEMM_SMEM_BYTES);

    const int gridM = MROWS / 128;   // 392
    dim3 blk(256);
    dim3 gq(1152 / 128, gridM);
    dim3 g3(384 / 128, gridM);
    const int nact4 = OS / 4;

    // launches 1-4: conversions
    cvt_w_kernel<<<1152, 256>>>(qkv_w, vscale_w, vshift_w, proj_x_w, proj_scale_w, proj_shift_w, p_whi);
    cvt_kernel<<<(nact4 + 255) / 256, 256>>>(x,     p_xhi,  p_xlo,  nact4);
    cvt_kernel<<<(nact4 + 255) / 256, 256>>>(scale, p_schi, p_sclo, nact4);
    cvt_kernel<<<(nact4 + 255) / 256, 256>>>(shift, p_shhi, p_shlo, nact4);

    // launch 5: vscale GEMM ; launch 6: qkv GEMM (ncu profiles launch #6)
    gemm_mma_kernel<<<g3, blk, GEMM_SMEM_BYTES>>>(p_schi, p_sclo, p_whi + WOFF_VS,  vscale_b, p_vs,  384);
    gemm_mma_kernel<<<gq, blk, GEMM_SMEM_BYTES>>>(p_xhi,  p_xlo,  p_whi + WOFF_QKV, qkv_b,    p_qkv, 1152);
    gemm_mma_kernel<<<g3, blk, GEMM_SMEM_BYTES>>>(p_shhi, p_shlo, p_whi + WOFF_VSH, vshift_b, p_vsh, 384);

    dim3 agrid(BW, NHEAD);
    attn_kernel<<<agrid, 256>>>(mask, rpb_table);

    gemm_mma_kernel<<<g3, blk, GEMM_SMEM_BYTES>>>(p_ohi,          p_olo,          p_whi + WOFF_PX,  proj_x_b,     out,          384);
    gemm_mma_kernel<<<g3, blk, GEMM_SMEM_BYTES>>>(p_ohi + OS,     p_olo + OS,     p_whi + WOFF_PS,  proj_scale_b, out + OS,     384);
    gemm_mma_kernel<<<g3, blk, GEMM_SMEM_BYTES>>>(p_ohi + 2 * OS, p_olo + 2 * OS, p_whi + WOFF_PSH, proj_shift_b, out + 2 * OS, 384);
}